// round 8
// baseline (speedup 1.0000x reference)
#include <cuda_runtime.h>
#include <cuda_fp16.h>

#define NN 50000
#define EE 800000
#define D 96
#define ED 32
#define NB 391   // ceil(NN/128)

typedef unsigned long long ull;
typedef long long ll;

#define PACK2(d, lo, hi)  asm("mov.b64 %0, {%1, %2};" : "=l"(d) : "f"(lo), "f"(hi))
#define UNPACK2(lo, hi, s) asm("mov.b64 {%0, %1}, %2;" : "=f"(lo), "=f"(hi) : "l"(s))
#define FMA2(d, a, b, c)  asm("fma.rn.f32x2 %0, %1, %2, %3;" : "=l"(d) : "l"(a), "l"(b), "l"(c))

// ---------------- static device scratch ----------------
__device__ __align__(16) int    g_deg[NN];
__device__ __align__(16) int    g_part[512];
__device__ __align__(16) int    g_rowptr[NN + 1];
__device__ __align__(16) int    g_fill[NN];
__device__ __align__(16) int    g_pos[EE];                 // edge id -> CSR position
__device__ __align__(16) __half g_msg[(ll)EE * D];         // CSR-ordered fp16 messages (154 MB)
__device__ __align__(16) float  g_h [NN * D];
__device__ __align__(16) float  g_h1[NN * D];
__device__ __align__(16) float  g_h2[NN * D];
__device__ __align__(16) float  g_sum[D];
__device__ __align__(16) float  g_sumsq[D];
__device__ int g_is64;

__device__ __forceinline__ int load_idx(const void* ei, int pos) {
    if (g_is64) return (int)((const long long*)ei)[pos];
    return ((const int*)ei)[pos];
}
__device__ __forceinline__ int clampN(int v, int n) {
    return v < 0 ? 0 : (v >= n ? n - 1 : v);
}

// ---------------- init: dtype detect + zero ----------------
__global__ void k_init(const unsigned int* __restrict__ w) {
    int i = blockIdx.x * blockDim.x + threadIdx.x;
    if (blockIdx.x == 0 && threadIdx.x < 32) {
        unsigned v = w[2 * threadIdx.x + 1];
        unsigned b = __ballot_sync(0xffffffffu, v != 0u);
        if (threadIdx.x == 0) g_is64 = (b == 0u) ? 1 : 0;
    }
    if (i < NN) g_deg[i] = 0;
    if (i < D) { g_sum[i] = 0.f; g_sumsq[i] = 0.f; }
}

// ---------------- CSR build ----------------
__global__ void k_count(const void* __restrict__ ei) {
    int e = blockIdx.x * blockDim.x + threadIdx.x;
    if (e < EE) {
        int dst = load_idx(ei, EE + e);
        if ((unsigned)dst < (unsigned)NN) atomicAdd(&g_deg[dst], 1);
    }
}

__global__ void k_scan1() {
    __shared__ int s[128];
    int t = threadIdx.x;
    int i = blockIdx.x * 128 + t;
    s[t] = (i < NN) ? g_deg[i] : 0;
    __syncthreads();
    for (int off = 64; off; off >>= 1) {
        if (t < off) s[t] += s[t + off];
        __syncthreads();
    }
    if (t == 0) g_part[blockIdx.x] = s[0];
}

__global__ void k_scan2() {
    __shared__ int s[512];
    int t = threadIdx.x;
    s[t] = (t < NB) ? g_part[t] : 0;
    __syncthreads();
    for (int off = 1; off < 512; off <<= 1) {
        int u = (t >= off) ? s[t - off] : 0;
        __syncthreads();
        s[t] += u;
        __syncthreads();
    }
    if (t < NB) g_part[t] = s[t];
}

__global__ void k_scan3() {
    __shared__ int s[128];
    int t = threadIdx.x;
    int i = blockIdx.x * 128 + t;
    int v = (i < NN) ? g_deg[i] : 0;
    s[t] = v;
    __syncthreads();
    for (int off = 1; off < 128; off <<= 1) {
        int u = (t >= off) ? s[t - off] : 0;
        __syncthreads();
        s[t] += u;
        __syncthreads();
    }
    int base = blockIdx.x ? g_part[blockIdx.x - 1] : 0;
    if (i < NN) {
        int ex = base + s[t] - v;
        g_rowptr[i] = ex;
        g_fill[i]   = ex;
        if (i == NN - 1) g_rowptr[NN] = base + s[t];
    }
}

__global__ void k_fill(const void* __restrict__ ei) {
    int e = blockIdx.x * blockDim.x + threadIdx.x;
    if (e < EE) {
        int dst = load_idx(ei, EE + e);
        int pos = 0;
        if ((unsigned)dst < (unsigned)NN) pos = atomicAdd(&g_fill[dst], 1);
        g_pos[e] = clampN(pos, EE);        // sequential write only
    }
}

// ---------------- Phase A: fused edge message ----------------
// proj = ea@We + be (FFMA2, edge-ordered streaming), transpose via smem,
// then msg = relu(x[src] + proj) stored fp16 at CSR position.
__global__ void __launch_bounds__(256) k_edgemsg(
    const float* __restrict__ ea, const void* __restrict__ ei,
    const float* __restrict__ We, const float* __restrict__ be,
    const float* __restrict__ x)
{
    __shared__ __align__(16) float We_s[ED * D];     // 12 KB
    __shared__ __align__(16) float u_buf[256 * ED];  // 32 KB: XOR-swizzled ea tile; reused 64x97 out
    __shared__ int pos_s[256];
    __shared__ int src_s[256];

    int tid = threadIdx.x;
    ll e0 = (ll)blockIdx.x * 256;

    pos_s[tid] = clampN(g_pos[e0 + tid], EE);
    src_s[tid] = clampN(load_idx(ei, (int)(e0 + tid)), NN);
    for (int i = tid; i < ED * D; i += 256) We_s[i] = We[i];
    for (int i = tid; i < 256 * ED; i += 256) {
        int r = i >> 5, c = i & 31;
        u_buf[r * 32 + (c ^ (r & 31))] = ea[(e0 + r) * ED + c];  // coalesced stream, swizzled
    }
    __syncthreads();

    ull acc[48];
    const float2* be2 = (const float2*)be;
#pragma unroll
    for (int j = 0; j < 48; j++) { float2 b = __ldg(&be2[j]); PACK2(acc[j], b.x, b.y); }

    {
        const float* ea_base = u_buf + tid * 32;
        int sw = tid & 31;
#pragma unroll 2
        for (int k = 0; k < ED; k++) {
            float hk = ea_base[k ^ sw];
            ull hk2; PACK2(hk2, hk, hk);
            const ulonglong2* w2 = (const ulonglong2*)(We_s + k * D);
#pragma unroll
            for (int j = 0; j < 24; j++) {
                ulonglong2 w = w2[j];
                FMA2(acc[2 * j],     hk2, w.x, acc[2 * j]);
                FMA2(acc[2 * j + 1], hk2, w.y, acc[2 * j + 1]);
            }
        }
    }

    // 4 quarters of 64 edges: transpose -> add x (row-coalesced) -> relu -> fp16 scatter store
    const float2* x2 = (const float2*)x;
    __half2* msg2 = (__half2*)g_msg;
    for (int q = 0; q < 4; q++) {
        __syncthreads();
        if ((tid >> 6) == q) {
            int base = (tid & 63) * 97;               // bank = (row+col) % 32, conflict-free
#pragma unroll
            for (int j = 0; j < 48; j++) {
                float lo, hi;
                UNPACK2(lo, hi, acc[j]);
                u_buf[base + 2 * j]     = lo;
                u_buf[base + 2 * j + 1] = hi;
            }
        }
        __syncthreads();
#pragma unroll
        for (int it = 0; it < 12; it++) {             // 64 rows * 48 half2 / 256 threads
            int f = it * 256 + tid;
            int row = f / 48, c2 = f - row * 48;
            int src = src_s[q * 64 + row];
            float2 xv = x2[(ll)src * 48 + c2];
            float v0 = fmaxf(u_buf[row * 97 + 2 * c2]     + xv.x, 0.f);
            float v1 = fmaxf(u_buf[row * 97 + 2 * c2 + 1] + xv.y, 0.f);
            msg2[(ll)pos_s[q * 64 + row] * 48 + c2] = __floats2half2_rn(v0, v1);
        }
    }
}

// ---------------- Phase B: pure streaming segmented sum ----------------
__global__ void __launch_bounds__(256) k_aggr(const float* __restrict__ x)
{
    int warp = (blockIdx.x * blockDim.x + threadIdx.x) >> 5;
    int lane = threadIdx.x & 31;
    if (warp >= NN) return;

    int node = warp;
    int beg = g_rowptr[node], end = g_rowptr[node + 1];
    float a0 = 0.f, a1 = 0.f, a2 = 0.f;
    float b0 = 0.f, b1 = 0.f, b2 = 0.f;
    int p = beg;
    for (; p + 2 <= end; p += 2) {
        const __half* m = g_msg + (ll)p * D;
        a0 += __half2float(m[lane]);
        a1 += __half2float(m[lane + 32]);
        a2 += __half2float(m[lane + 64]);
        b0 += __half2float(m[D + lane]);
        b1 += __half2float(m[D + lane + 32]);
        b2 += __half2float(m[D + lane + 64]);
    }
    if (p < end) {
        const __half* m = g_msg + (ll)p * D;
        a0 += __half2float(m[lane]);
        a1 += __half2float(m[lane + 32]);
        a2 += __half2float(m[lane + 64]);
    }
    const float* xn = x + (ll)node * D;
    g_h[node * D + lane]      = xn[lane]      + a0 + b0;
    g_h[node * D + lane + 32] = xn[lane + 32] + a1 + b1;
    g_h[node * D + lane + 64] = xn[lane + 64] + a2 + b2;
}

// ---------------- dense layer (FFMA2): stage 0: g_h->g_h1 (ReLU); stage 1: g_h1->g_h2 (+stats) ----------------
__global__ void __launch_bounds__(128) k_mlp(
    const float* __restrict__ W, const float* __restrict__ bias, int stage)
{
    __shared__ __align__(16) float Ws[32 * D];
    __shared__ __align__(16) float hs[128 * 33];

    const float* hin  = (stage == 0) ? g_h  : g_h1;
    float*       hout = (stage == 0) ? g_h1 : g_h2;

    int tid  = threadIdx.x;
    int base = blockIdx.x * 128;
    int node = base + tid;
    bool valid = node < NN;

    ull acc[48];
#pragma unroll
    for (int j = 0; j < 48; j++) { float c0 = bias[2 * j], c1 = bias[2 * j + 1]; PACK2(acc[j], c0, c1); }

    for (int kt = 0; kt < 3; kt++) {
        for (int i = tid; i < 32 * D; i += 128) Ws[i] = W[kt * 32 * D + i];
        for (int i = tid; i < 128 * 32; i += 128) {
            int r = i >> 5, kk = i & 31;
            int nd = base + r;
            hs[r * 33 + kk] = (nd < NN) ? hin[(ll)nd * D + kt * 32 + kk] : 0.f;
        }
        __syncthreads();

#pragma unroll 2
        for (int kk = 0; kk < 32; kk++) {
            float hk = hs[tid * 33 + kk];
            ull hk2; PACK2(hk2, hk, hk);
            const ulonglong2* w2 = (const ulonglong2*)(Ws + kk * D);
#pragma unroll
            for (int j = 0; j < 24; j++) {
                ulonglong2 w = w2[j];
                FMA2(acc[2 * j],     hk2, w.x, acc[2 * j]);
                FMA2(acc[2 * j + 1], hk2, w.y, acc[2 * j + 1]);
            }
        }
        __syncthreads();
    }

    float v[D];
#pragma unroll
    for (int j = 0; j < 48; j++) UNPACK2(v[2 * j], v[2 * j + 1], acc[j]);

    if (stage == 0) {
#pragma unroll
        for (int j = 0; j < D; j++) v[j] = fmaxf(v[j], 0.f);
    }
    if (valid) {
        float4* out4 = (float4*)(hout + (ll)node * D);
#pragma unroll
        for (int j4 = 0; j4 < D / 4; j4++)
            out4[j4] = make_float4(v[4 * j4], v[4 * j4 + 1], v[4 * j4 + 2], v[4 * j4 + 3]);
    }
    if (stage == 1) {
#pragma unroll
        for (int j = 0; j < D; j++) {
            float s1 = valid ? v[j] : 0.f;
            float s2 = s1 * s1;
            for (int off = 16; off; off >>= 1) {
                s1 += __shfl_down_sync(0xffffffffu, s1, off);
                s2 += __shfl_down_sync(0xffffffffu, s2, off);
            }
            if ((tid & 31) == 0) {
                atomicAdd(&g_sum[j],   s1);
                atomicAdd(&g_sumsq[j], s2);
            }
        }
    }
}

// ---------------- batchnorm + relu ----------------
__global__ void k_bn(const float* __restrict__ gamma,
                     const float* __restrict__ beta,
                     float* __restrict__ out)
{
    int i = blockIdx.x * blockDim.x + threadIdx.x;
    const int TOT4 = NN * D / 4;
    if (i >= TOT4) return;
    int c = (i * 4) % D;
    const float invN = 1.0f / (float)NN;
    float4 h = ((const float4*)g_h2)[i];
    float hv[4] = {h.x, h.y, h.z, h.w};
    float o[4];
#pragma unroll
    for (int u = 0; u < 4; u++) {
        int cc = c + u;
        float mean = g_sum[cc] * invN;
        float var  = g_sumsq[cc] * invN - mean * mean;
        float inv  = rsqrtf(var + 1e-5f);
        o[u] = fmaxf((hv[u] - mean) * inv * gamma[cc] + beta[cc], 0.f);
    }
    ((float4*)out)[i] = make_float4(o[0], o[1], o[2], o[3]);
}

// ---------------- launch ----------------
extern "C" void kernel_launch(void* const* d_in, const int* in_sizes, int n_in,
                              void* d_out, int out_size)
{
    const float* x     = (const float*)d_in[0];
    const void*  ei    = d_in[1];
    const float* ea    = (const float*)d_in[2];
    const float* We    = (const float*)d_in[3];
    const float* be    = (const float*)d_in[4];
    const float* W1    = (const float*)d_in[5];
    const float* b1    = (const float*)d_in[6];
    const float* W2    = (const float*)d_in[7];
    const float* b2    = (const float*)d_in[8];
    const float* gamma = (const float*)d_in[9];
    const float* beta  = (const float*)d_in[10];
    float*       out   = (float*)d_out;

    k_init   <<<(NN + 255) / 256, 256>>>((const unsigned int*)ei);
    k_count  <<<(EE + 255) / 256, 256>>>(ei);
    k_scan1  <<<NB, 128>>>();
    k_scan2  <<<1, 512>>>();
    k_scan3  <<<NB, 128>>>();
    k_fill   <<<(EE + 255) / 256, 256>>>(ei);
    k_edgemsg<<<EE / 256, 256>>>(ea, ei, We, be, x);
    k_aggr   <<<NN / 8, 256>>>(x);
    k_mlp    <<<(NN + 127) / 128, 128>>>(W1, b1, 0);
    k_mlp    <<<(NN + 127) / 128, 128>>>(W2, b2, 1);
    k_bn     <<<(NN * D / 4 + 255) / 256, 256>>>(gamma, beta, out);
}

// round 9
// speedup vs baseline: 1.0516x; 1.0516x over previous
#include <cuda_runtime.h>
#include <cuda_bf16.h>

#define NN 50000
#define EE 800000
#define D 96
#define ED 32
#define NB 391   // ceil(NN/128)

typedef unsigned long long ull;

#define PACK2(d, lo, hi)  asm("mov.b64 %0, {%1, %2};" : "=l"(d) : "f"(lo), "f"(hi))
#define UNPACK2(lo, hi, s) asm("mov.b64 {%0, %1}, %2;" : "=f"(lo), "=f"(hi) : "l"(s))
#define FMA2(d, a, b, c)  asm("fma.rn.f32x2 %0, %1, %2, %3;" : "=l"(d) : "l"(a), "l"(b), "l"(c))

// ---------------- static device scratch ----------------
__device__ __align__(16) int   g_deg[NN];
__device__ __align__(16) int   g_part[512];
__device__ __align__(16) int   g_rowptr[NN + 1];
__device__ __align__(16) int   g_fill[NN];
__device__ __align__(16) int   g_eidx[EE];   // CSR position -> edge id
__device__ __align__(16) int   g_src[EE];    // CSR position -> src node
__device__ __align__(16) float g_proj[(long long)EE * D];  // edge-ordered projections
__device__ __align__(16) float g_h [NN * D];
__device__ __align__(16) float g_h1[NN * D];
__device__ __align__(16) float g_h2[NN * D];
__device__ __align__(16) float g_sum[D];
__device__ __align__(16) float g_sumsq[D];
__device__ int g_is64;

__device__ __forceinline__ int load_idx(const void* ei, int pos) {
    if (g_is64) return (int)((const long long*)ei)[pos];
    return ((const int*)ei)[pos];
}
__device__ __forceinline__ int clampN(int v, int n) {
    return v < 0 ? 0 : (v >= n ? n - 1 : v);
}

// ---------------- init: dtype detect + zero ----------------
__global__ void k_init(const unsigned int* __restrict__ w) {
    int i = blockIdx.x * blockDim.x + threadIdx.x;
    if (blockIdx.x == 0 && threadIdx.x < 32) {
        unsigned v = w[2 * threadIdx.x + 1];
        unsigned b = __ballot_sync(0xffffffffu, v != 0u);
        if (threadIdx.x == 0) g_is64 = (b == 0u) ? 1 : 0;
    }
    if (i < NN) g_deg[i] = 0;
    if (i < D) { g_sum[i] = 0.f; g_sumsq[i] = 0.f; }
}

// ---------------- CSR build ----------------
__global__ void k_count(const void* __restrict__ ei) {
    int e = blockIdx.x * blockDim.x + threadIdx.x;
    if (e < EE) {
        int dst = load_idx(ei, EE + e);
        if ((unsigned)dst < (unsigned)NN) atomicAdd(&g_deg[dst], 1);
    }
}

__global__ void k_scan1() {
    __shared__ int s[128];
    int t = threadIdx.x;
    int i = blockIdx.x * 128 + t;
    s[t] = (i < NN) ? g_deg[i] : 0;
    __syncthreads();
    for (int off = 64; off; off >>= 1) {
        if (t < off) s[t] += s[t + off];
        __syncthreads();
    }
    if (t == 0) g_part[blockIdx.x] = s[0];
}

__global__ void k_scan2() {
    __shared__ int s[512];
    int t = threadIdx.x;
    s[t] = (t < NB) ? g_part[t] : 0;
    __syncthreads();
    for (int off = 1; off < 512; off <<= 1) {
        int u = (t >= off) ? s[t - off] : 0;
        __syncthreads();
        s[t] += u;
        __syncthreads();
    }
    if (t < NB) g_part[t] = s[t];
}

__global__ void k_scan3() {
    __shared__ int s[128];
    int t = threadIdx.x;
    int i = blockIdx.x * 128 + t;
    int v = (i < NN) ? g_deg[i] : 0;
    s[t] = v;
    __syncthreads();
    for (int off = 1; off < 128; off <<= 1) {
        int u = (t >= off) ? s[t - off] : 0;
        __syncthreads();
        s[t] += u;
        __syncthreads();
    }
    int base = blockIdx.x ? g_part[blockIdx.x - 1] : 0;
    if (i < NN) {
        int ex = base + s[t] - v;
        g_rowptr[i] = ex;
        g_fill[i]   = ex;
        if (i == NN - 1) g_rowptr[NN] = base + s[t];
    }
}

__global__ void k_fill(const void* __restrict__ ei) {
    int e = blockIdx.x * blockDim.x + threadIdx.x;
    if (e < EE) {
        int dst = load_idx(ei, EE + e);
        if ((unsigned)dst < (unsigned)NN) {
            int pos = atomicAdd(&g_fill[dst], 1);
            if ((unsigned)pos < (unsigned)EE) {
                g_eidx[pos] = e;
                g_src[pos]  = clampN(load_idx(ei, e), NN);
            }
        }
    }
}

// ---------------- Phase A: edge projection GEMM (edge-ordered, transposed coalesced stores) ----------------
__global__ void __launch_bounds__(256) k_edgemsg(
    const float* __restrict__ ea, const float* __restrict__ We,
    const float* __restrict__ be)
{
    __shared__ __align__(16) float We_s[ED * D];     // 12 KB
    __shared__ __align__(16) float u_buf[256 * 33];  // 33.8 KB: ea tile, then out quarters (64*97)
    __shared__ __align__(16) float be_s[D];

    int tid = threadIdx.x;
    long long e0 = (long long)blockIdx.x * 256;

    for (int i = tid; i < ED * D; i += 256) We_s[i] = We[i];
    if (tid < D) be_s[tid] = be[tid];
    for (int i = tid; i < 256 * ED; i += 256) {
        int r = i >> 5, c = i & 31;
        u_buf[r * 33 + c] = ea[(e0 + r) * ED + c];    // sequential stream, coalesced
    }
    __syncthreads();

    ull acc[48];
#pragma unroll
    for (int j = 0; j < 48; j++) PACK2(acc[j], be_s[2 * j], be_s[2 * j + 1]);

#pragma unroll 2
    for (int k = 0; k < ED; k++) {
        float hk = u_buf[tid * 33 + k];
        ull hk2; PACK2(hk2, hk, hk);
        const ulonglong2* w2 = (const ulonglong2*)(We_s + k * D);
#pragma unroll
        for (int j = 0; j < 24; j++) {
            ulonglong2 w = w2[j];
            FMA2(acc[2 * j],     hk2, w.x, acc[2 * j]);
            FMA2(acc[2 * j + 1], hk2, w.y, acc[2 * j + 1]);
        }
    }

    // transpose through smem in 4 quarters of 64 edges; coalesced global stores
    for (int q = 0; q < 4; q++) {
        __syncthreads();
        if ((tid >> 6) == q) {
            int base = (tid & 63) * 97;               // bank = (row+col) % 32, conflict-free
#pragma unroll
            for (int j = 0; j < 48; j++) {
                float lo, hi;
                UNPACK2(lo, hi, acc[j]);
                u_buf[base + 2 * j]     = lo;
                u_buf[base + 2 * j + 1] = hi;
            }
        }
        __syncthreads();
        long long gbase = (e0 + (long long)q * 64) * D;
#pragma unroll
        for (int it = 0; it < 24; it++) {             // 64*96/256 = 24
            int f = it * 256 + tid;
            int row = f / D, col = f - row * D;
            g_proj[gbase + f] = u_buf[row * 97 + col];
        }
    }
}

// ---------------- Phase B: pull aggregation (3 warps per node: warp t owns dims [32t,32t+32)) ----------------
__global__ void __launch_bounds__(256) k_aggr(const float* __restrict__ x)
{
    int gw   = (blockIdx.x * blockDim.x + threadIdx.x) >> 5;
    int lane = threadIdx.x & 31;
    if (gw >= 3 * NN) return;
    int node = gw / 3;
    int off  = (gw - node * 3) * 32 + lane;

    int beg = g_rowptr[node], end = g_rowptr[node + 1];
    float a = 0.f, b = 0.f;
    int p = beg;
    for (; p + 2 <= end; p += 2) {
        int e0 = clampN(g_eidx[p],     EE);
        int e1 = clampN(g_eidx[p + 1], EE);
        int s0 = g_src[p], s1 = g_src[p + 1];
        float p0 = g_proj[(long long)e0 * D + off];
        float p1 = g_proj[(long long)e1 * D + off];
        float x0 = x[(long long)s0 * D + off];
        float x1 = x[(long long)s1 * D + off];
        a += fmaxf(x0 + p0, 0.f);
        b += fmaxf(x1 + p1, 0.f);
    }
    if (p < end) {
        int e0 = clampN(g_eidx[p], EE);
        int s0 = g_src[p];
        a += fmaxf(x[(long long)s0 * D + off] + g_proj[(long long)e0 * D + off], 0.f);
    }
    g_h[node * D + off] = x[(long long)node * D + off] + a + b;
}

// ---------------- dense layer (FFMA2): stage 0: g_h->g_h1 (ReLU); stage 1: g_h1->g_h2 (+stats) ----------------
__global__ void __launch_bounds__(128) k_mlp(
    const float* __restrict__ W, const float* __restrict__ bias, int stage)
{
    __shared__ __align__(16) float Ws[32 * D];
    __shared__ __align__(16) float hs[128 * 33];

    const float* hin  = (stage == 0) ? g_h  : g_h1;
    float*       hout = (stage == 0) ? g_h1 : g_h2;

    int tid  = threadIdx.x;
    int base = blockIdx.x * 128;
    int node = base + tid;
    bool valid = node < NN;

    ull acc[48];
#pragma unroll
    for (int j = 0; j < 48; j++) { float c0 = bias[2 * j], c1 = bias[2 * j + 1]; PACK2(acc[j], c0, c1); }

    for (int kt = 0; kt < 3; kt++) {
        for (int i = tid; i < 32 * D; i += 128) Ws[i] = W[kt * 32 * D + i];
        for (int i = tid; i < 128 * 32; i += 128) {
            int r = i >> 5, kk = i & 31;
            int nd = base + r;
            hs[r * 33 + kk] = (nd < NN) ? hin[(long long)nd * D + kt * 32 + kk] : 0.f;
        }
        __syncthreads();

#pragma unroll 2
        for (int kk = 0; kk < 32; kk++) {
            float hk = hs[tid * 33 + kk];
            ull hk2; PACK2(hk2, hk, hk);
            const ulonglong2* w2 = (const ulonglong2*)(Ws + kk * D);
#pragma unroll
            for (int j = 0; j < 24; j++) {
                ulonglong2 w = w2[j];
                FMA2(acc[2 * j],     hk2, w.x, acc[2 * j]);
                FMA2(acc[2 * j + 1], hk2, w.y, acc[2 * j + 1]);
            }
        }
        __syncthreads();
    }

    float v[D];
#pragma unroll
    for (int j = 0; j < 48; j++) UNPACK2(v[2 * j], v[2 * j + 1], acc[j]);

    if (stage == 0) {
#pragma unroll
        for (int j = 0; j < D; j++) v[j] = fmaxf(v[j], 0.f);
    }
    if (valid) {
        float4* out4 = (float4*)(hout + (long long)node * D);
#pragma unroll
        for (int j4 = 0; j4 < D / 4; j4++)
            out4[j4] = make_float4(v[4 * j4], v[4 * j4 + 1], v[4 * j4 + 2], v[4 * j4 + 3]);
    }
    if (stage == 1) {
#pragma unroll
        for (int j = 0; j < D; j++) {
            float s1 = valid ? v[j] : 0.f;
            float s2 = s1 * s1;
            for (int off = 16; off; off >>= 1) {
                s1 += __shfl_down_sync(0xffffffffu, s1, off);
                s2 += __shfl_down_sync(0xffffffffu, s2, off);
            }
            if ((tid & 31) == 0) {
                atomicAdd(&g_sum[j],   s1);
                atomicAdd(&g_sumsq[j], s2);
            }
        }
    }
}

// ---------------- batchnorm + relu ----------------
__global__ void k_bn(const float* __restrict__ gamma,
                     const float* __restrict__ beta,
                     float* __restrict__ out)
{
    int i = blockIdx.x * blockDim.x + threadIdx.x;
    const int TOT4 = NN * D / 4;
    if (i >= TOT4) return;
    int c = (i * 4) % D;
    const float invN = 1.0f / (float)NN;
    float4 h = ((const float4*)g_h2)[i];
    float hv[4] = {h.x, h.y, h.z, h.w};
    float o[4];
#pragma unroll
    for (int u = 0; u < 4; u++) {
        int cc = c + u;
        float mean = g_sum[cc] * invN;
        float var  = g_sumsq[cc] * invN - mean * mean;
        float inv  = rsqrtf(var + 1e-5f);
        o[u] = fmaxf((hv[u] - mean) * inv * gamma[cc] + beta[cc], 0.f);
    }
    ((float4*)out)[i] = make_float4(o[0], o[1], o[2], o[3]);
}

// ---------------- launch ----------------
extern "C" void kernel_launch(void* const* d_in, const int* in_sizes, int n_in,
                              void* d_out, int out_size)
{
    const float* x     = (const float*)d_in[0];
    const void*  ei    = d_in[1];
    const float* ea    = (const float*)d_in[2];
    const float* We    = (const float*)d_in[3];
    const float* be    = (const float*)d_in[4];
    const float* W1    = (const float*)d_in[5];
    const float* b1    = (const float*)d_in[6];
    const float* W2    = (const float*)d_in[7];
    const float* b2    = (const float*)d_in[8];
    const float* gamma = (const float*)d_in[9];
    const float* beta  = (const float*)d_in[10];
    float*       out   = (float*)d_out;

    k_init   <<<(NN + 255) / 256, 256>>>((const unsigned int*)ei);
    k_count  <<<(EE + 255) / 256, 256>>>(ei);
    k_scan1  <<<NB, 128>>>();
    k_scan2  <<<1, 512>>>();
    k_scan3  <<<NB, 128>>>();
    k_fill   <<<(EE + 255) / 256, 256>>>(ei);
    k_edgemsg<<<EE / 256, 256>>>(ea, We, be);
    k_aggr   <<<(3 * NN + 7) / 8, 256>>>(x);          // 3 warps per node
    k_mlp    <<<(NN + 127) / 128, 128>>>(W1, b1, 0);
    k_mlp    <<<(NN + 127) / 128, 128>>>(W2, b2, 1);
    k_bn     <<<(NN * D / 4 + 255) / 256, 256>>>(gamma, beta, out);
}

// round 10
// speedup vs baseline: 1.0828x; 1.0296x over previous
#include <cuda_runtime.h>
#include <cuda_bf16.h>

#define NN 50000
#define EE 800000
#define D 96
#define ED 32
#define NB 391   // ceil(NN/128)

typedef unsigned long long ull;

#define PACK2(d, lo, hi)  asm("mov.b64 %0, {%1, %2};" : "=l"(d) : "f"(lo), "f"(hi))
#define UNPACK2(lo, hi, s) asm("mov.b64 {%0, %1}, %2;" : "=f"(lo), "=f"(hi) : "l"(s))
#define FMA2(d, a, b, c)  asm("fma.rn.f32x2 %0, %1, %2, %3;" : "=l"(d) : "l"(a), "l"(b), "l"(c))

// ---------------- static device scratch ----------------
__device__ __align__(16) int   g_deg[NN];
__device__ __align__(16) int   g_part[512];
__device__ __align__(16) int   g_rowptr[NN + 1];
__device__ __align__(16) int   g_fill[NN];
__device__ __align__(16) int   g_eidx[EE];   // CSR position -> edge id
__device__ __align__(16) int   g_src[EE];    // CSR position -> src node
__device__ __align__(16) float g_proj[(long long)EE * D];  // edge-ordered projections
__device__ __align__(16) float g_h [NN * D];
__device__ __align__(16) float g_h1[NN * D];
__device__ __align__(16) float g_h2[NN * D];
__device__ __align__(16) float g_sum[D];
__device__ __align__(16) float g_sumsq[D];
__device__ int g_is64;

__device__ __forceinline__ int load_idx(const void* ei, int pos) {
    if (g_is64) return (int)((const long long*)ei)[pos];
    return ((const int*)ei)[pos];
}
__device__ __forceinline__ int clampN(int v, int n) {
    return v < 0 ? 0 : (v >= n ? n - 1 : v);
}

// ---------------- init: dtype detect + zero ----------------
__global__ void k_init(const unsigned int* __restrict__ w) {
    int i = blockIdx.x * blockDim.x + threadIdx.x;
    if (blockIdx.x == 0 && threadIdx.x < 32) {
        unsigned v = w[2 * threadIdx.x + 1];
        unsigned b = __ballot_sync(0xffffffffu, v != 0u);
        if (threadIdx.x == 0) g_is64 = (b == 0u) ? 1 : 0;
    }
    if (i < NN) g_deg[i] = 0;
    if (i < D) { g_sum[i] = 0.f; g_sumsq[i] = 0.f; }
}

// ---------------- CSR build ----------------
__global__ void k_count(const void* __restrict__ ei) {
    int e = blockIdx.x * blockDim.x + threadIdx.x;
    if (e < EE) {
        int dst = load_idx(ei, EE + e);
        if ((unsigned)dst < (unsigned)NN) atomicAdd(&g_deg[dst], 1);
    }
}

__global__ void k_scan1() {
    __shared__ int s[128];
    int t = threadIdx.x;
    int i = blockIdx.x * 128 + t;
    s[t] = (i < NN) ? g_deg[i] : 0;
    __syncthreads();
    for (int off = 64; off; off >>= 1) {
        if (t < off) s[t] += s[t + off];
        __syncthreads();
    }
    if (t == 0) g_part[blockIdx.x] = s[0];
}

__global__ void k_scan2() {
    __shared__ int s[512];
    int t = threadIdx.x;
    s[t] = (t < NB) ? g_part[t] : 0;
    __syncthreads();
    for (int off = 1; off < 512; off <<= 1) {
        int u = (t >= off) ? s[t - off] : 0;
        __syncthreads();
        s[t] += u;
        __syncthreads();
    }
    if (t < NB) g_part[t] = s[t];
}

__global__ void k_scan3() {
    __shared__ int s[128];
    int t = threadIdx.x;
    int i = blockIdx.x * 128 + t;
    int v = (i < NN) ? g_deg[i] : 0;
    s[t] = v;
    __syncthreads();
    for (int off = 1; off < 128; off <<= 1) {
        int u = (t >= off) ? s[t - off] : 0;
        __syncthreads();
        s[t] += u;
        __syncthreads();
    }
    int base = blockIdx.x ? g_part[blockIdx.x - 1] : 0;
    if (i < NN) {
        int ex = base + s[t] - v;
        g_rowptr[i] = ex;
        g_fill[i]   = ex;
        if (i == NN - 1) g_rowptr[NN] = base + s[t];
    }
}

__global__ void k_fill(const void* __restrict__ ei) {
    int e = blockIdx.x * blockDim.x + threadIdx.x;
    if (e < EE) {
        int dst = load_idx(ei, EE + e);
        if ((unsigned)dst < (unsigned)NN) {
            int pos = atomicAdd(&g_fill[dst], 1);
            if ((unsigned)pos < (unsigned)EE) {
                g_eidx[pos] = e;
                g_src[pos]  = clampN(load_idx(ei, e), NN);
            }
        }
    }
}

// ---------------- Phase A: edge projection GEMM (edge-ordered, transposed coalesced stores) ----------------
__global__ void __launch_bounds__(256) k_edgemsg(
    const float* __restrict__ ea, const float* __restrict__ We,
    const float* __restrict__ be)
{
    __shared__ __align__(16) float We_s[ED * D];     // 12 KB
    __shared__ __align__(16) float u_buf[256 * 33];  // 33.8 KB: ea tile, then out quarters (64*97)
    __shared__ __align__(16) float be_s[D];

    int tid = threadIdx.x;
    long long e0 = (long long)blockIdx.x * 256;

    for (int i = tid; i < ED * D; i += 256) We_s[i] = We[i];
    if (tid < D) be_s[tid] = be[tid];
    for (int i = tid; i < 256 * ED; i += 256) {
        int r = i >> 5, c = i & 31;
        u_buf[r * 33 + c] = ea[(e0 + r) * ED + c];    // sequential stream, coalesced
    }
    __syncthreads();

    ull acc[48];
#pragma unroll
    for (int j = 0; j < 48; j++) PACK2(acc[j], be_s[2 * j], be_s[2 * j + 1]);

#pragma unroll 2
    for (int k = 0; k < ED; k++) {
        float hk = u_buf[tid * 33 + k];
        ull hk2; PACK2(hk2, hk, hk);
        const ulonglong2* w2 = (const ulonglong2*)(We_s + k * D);
#pragma unroll
        for (int j = 0; j < 24; j++) {
            ulonglong2 w = w2[j];
            FMA2(acc[2 * j],     hk2, w.x, acc[2 * j]);
            FMA2(acc[2 * j + 1], hk2, w.y, acc[2 * j + 1]);
        }
    }

    // transpose through smem in 4 quarters of 64 edges; coalesced global stores
    for (int q = 0; q < 4; q++) {
        __syncthreads();
        if ((tid >> 6) == q) {
            int base = (tid & 63) * 97;               // bank = (row+col) % 32, conflict-free
#pragma unroll
            for (int j = 0; j < 48; j++) {
                float lo, hi;
                UNPACK2(lo, hi, acc[j]);
                u_buf[base + 2 * j]     = lo;
                u_buf[base + 2 * j + 1] = hi;
            }
        }
        __syncthreads();
        long long gbase = (e0 + (long long)q * 64) * D;
#pragma unroll
        for (int it = 0; it < 24; it++) {             // 64*96/256 = 24
            int f = it * 256 + tid;
            int row = f / D, col = f - row * D;
            g_proj[gbase + f] = u_buf[row * 97 + col];
        }
    }
}

// ---------------- Phase B: pull aggregation (warp per node) ----------------
__global__ void __launch_bounds__(256) k_aggr(const float* __restrict__ x)
{
    int warp = (blockIdx.x * blockDim.x + threadIdx.x) >> 5;
    int lane = threadIdx.x & 31;
    if (warp >= NN) return;

    int node = warp;
    int beg = g_rowptr[node], end = g_rowptr[node + 1];
    float a0 = 0.f, a1 = 0.f, a2 = 0.f;
    for (int p = beg; p < end; p++) {
        int e   = clampN(g_eidx[p], EE);
        int src = g_src[p];
        const float* pr = g_proj + (long long)e * D;
        const float* xs = x + (long long)src * D;
        a0 += fmaxf(xs[lane]      + pr[lane],      0.f);
        a1 += fmaxf(xs[lane + 32] + pr[lane + 32], 0.f);
        a2 += fmaxf(xs[lane + 64] + pr[lane + 64], 0.f);
    }
    const float* xn = x + (long long)node * D;
    g_h[node * D + lane]      = xn[lane]      + a0;
    g_h[node * D + lane + 32] = xn[lane + 32] + a1;
    g_h[node * D + lane + 64] = xn[lane + 64] + a2;
}

// ---------------- dense layer (FFMA2): stage 0: g_h->g_h1 (ReLU); stage 1: g_h1->g_h2 (+stats) ----------------
__global__ void __launch_bounds__(128) k_mlp(
    const float* __restrict__ W, const float* __restrict__ bias, int stage)
{
    __shared__ __align__(16) float Ws[32 * D];
    __shared__ __align__(16) float hs[128 * 33];

    const float* hin  = (stage == 0) ? g_h  : g_h1;
    float*       hout = (stage == 0) ? g_h1 : g_h2;

    int tid  = threadIdx.x;
    int base = blockIdx.x * 128;
    int node = base + tid;
    bool valid = node < NN;

    ull acc[48];
#pragma unroll
    for (int j = 0; j < 48; j++) { float c0 = bias[2 * j], c1 = bias[2 * j + 1]; PACK2(acc[j], c0, c1); }

    for (int kt = 0; kt < 3; kt++) {
        for (int i = tid; i < 32 * D; i += 128) Ws[i] = W[kt * 32 * D + i];
        for (int i = tid; i < 128 * 32; i += 128) {
            int r = i >> 5, kk = i & 31;
            int nd = base + r;
            hs[r * 33 + kk] = (nd < NN) ? hin[(long long)nd * D + kt * 32 + kk] : 0.f;
        }
        __syncthreads();

#pragma unroll 2
        for (int kk = 0; kk < 32; kk++) {
            float hk = hs[tid * 33 + kk];
            ull hk2; PACK2(hk2, hk, hk);
            const ulonglong2* w2 = (const ulonglong2*)(Ws + kk * D);
#pragma unroll
            for (int j = 0; j < 24; j++) {
                ulonglong2 w = w2[j];
                FMA2(acc[2 * j],     hk2, w.x, acc[2 * j]);
                FMA2(acc[2 * j + 1], hk2, w.y, acc[2 * j + 1]);
            }
        }
        __syncthreads();
    }

    float v[D];
#pragma unroll
    for (int j = 0; j < 48; j++) UNPACK2(v[2 * j], v[2 * j + 1], acc[j]);

    if (stage == 0) {
#pragma unroll
        for (int j = 0; j < D; j++) v[j] = fmaxf(v[j], 0.f);
    }
    if (valid) {
        float4* out4 = (float4*)(hout + (long long)node * D);
#pragma unroll
        for (int j4 = 0; j4 < D / 4; j4++)
            out4[j4] = make_float4(v[4 * j4], v[4 * j4 + 1], v[4 * j4 + 2], v[4 * j4 + 3]);
    }
    if (stage == 1) {
#pragma unroll
        for (int j = 0; j < D; j++) {
            float s1 = valid ? v[j] : 0.f;
            float s2 = s1 * s1;
            for (int off = 16; off; off >>= 1) {
                s1 += __shfl_down_sync(0xffffffffu, s1, off);
                s2 += __shfl_down_sync(0xffffffffu, s2, off);
            }
            if ((tid & 31) == 0) {
                atomicAdd(&g_sum[j],   s1);
                atomicAdd(&g_sumsq[j], s2);
            }
        }
    }
}

// ---------------- batchnorm + relu ----------------
__global__ void k_bn(const float* __restrict__ gamma,
                     const float* __restrict__ beta,
                     float* __restrict__ out)
{
    int i = blockIdx.x * blockDim.x + threadIdx.x;
    const int TOT4 = NN * D / 4;
    if (i >= TOT4) return;
    int c = (i * 4) % D;
    const float invN = 1.0f / (float)NN;
    float4 h = ((const float4*)g_h2)[i];
    float hv[4] = {h.x, h.y, h.z, h.w};
    float o[4];
#pragma unroll
    for (int u = 0; u < 4; u++) {
        int cc = c + u;
        float mean = g_sum[cc] * invN;
        float var  = g_sumsq[cc] * invN - mean * mean;
        float inv  = rsqrtf(var + 1e-5f);
        o[u] = fmaxf((hv[u] - mean) * inv * gamma[cc] + beta[cc], 0.f);
    }
    ((float4*)out)[i] = make_float4(o[0], o[1], o[2], o[3]);
}

// ---------------- launch (edgemsg hoisted to launch index 3 so ncu captures it) ----------------
extern "C" void kernel_launch(void* const* d_in, const int* in_sizes, int n_in,
                              void* d_out, int out_size)
{
    const float* x     = (const float*)d_in[0];
    const void*  ei    = d_in[1];
    const float* ea    = (const float*)d_in[2];
    const float* We    = (const float*)d_in[3];
    const float* be    = (const float*)d_in[4];
    const float* W1    = (const float*)d_in[5];
    const float* b1    = (const float*)d_in[6];
    const float* W2    = (const float*)d_in[7];
    const float* b2    = (const float*)d_in[8];
    const float* gamma = (const float*)d_in[9];
    const float* beta  = (const float*)d_in[10];
    float*       out   = (float*)d_out;

    k_init   <<<(NN + 255) / 256, 256>>>((const unsigned int*)ei);   // 0
    k_count  <<<(EE + 255) / 256, 256>>>(ei);                        // 1
    k_scan1  <<<NB, 128>>>();                                        // 2
    k_edgemsg<<<EE / 256, 256>>>(ea, We, be);                        // 3  <- profiled slot
    k_scan2  <<<1, 512>>>();                                         // 4
    k_scan3  <<<NB, 128>>>();                                        // 5
    k_fill   <<<(EE + 255) / 256, 256>>>(ei);                        // 6
    k_aggr   <<<NN / 8, 256>>>(x);                                   // 7
    k_mlp    <<<(NN + 127) / 128, 128>>>(W1, b1, 0);                 // 8
    k_mlp    <<<(NN + 127) / 128, 128>>>(W2, b2, 1);                 // 9
    k_bn     <<<(NN * D / 4 + 255) / 256, 256>>>(gamma, beta, out);  // 10
}

// round 11
// speedup vs baseline: 1.1411x; 1.0539x over previous
#include <cuda_runtime.h>
#include <cuda_bf16.h>

#define NN 50000
#define EE 800000
#define D 96
#define ED 32
#define NB 391   // ceil(NN/128)

typedef unsigned long long ull;

#define PACK2(d, lo, hi)  asm("mov.b64 %0, {%1, %2};" : "=l"(d) : "f"(lo), "f"(hi))
#define UNPACK2(lo, hi, s) asm("mov.b64 {%0, %1}, %2;" : "=f"(lo), "=f"(hi) : "l"(s))
#define FMA2(d, a, b, c)  asm("fma.rn.f32x2 %0, %1, %2, %3;" : "=l"(d) : "l"(a), "l"(b), "l"(c))

// ---------------- static device scratch ----------------
__device__ __align__(16) int   g_deg[NN];
__device__ __align__(16) int   g_part[512];
__device__ __align__(16) int   g_rowptr[NN + 1];
__device__ __align__(16) int   g_fill[NN];
__device__ __align__(16) int   g_eidx[EE];   // CSR position -> edge id
__device__ __align__(16) int   g_src[EE];    // CSR position -> src node
__device__ __align__(16) float g_proj[(long long)EE * D];  // edge-ordered projections
__device__ __align__(16) float g_h [NN * D];
__device__ __align__(16) float g_h1[NN * D];
__device__ __align__(16) float g_h2[NN * D];
__device__ __align__(16) float g_sum[D];
__device__ __align__(16) float g_sumsq[D];
__device__ int g_is64;

__device__ __forceinline__ int load_idx(const void* ei, int pos) {
    if (g_is64) return (int)((const long long*)ei)[pos];
    return ((const int*)ei)[pos];
}
__device__ __forceinline__ int clampN(int v, int n) {
    return v < 0 ? 0 : (v >= n ? n - 1 : v);
}

// ---------------- init: dtype detect + zero ----------------
__global__ void k_init(const unsigned int* __restrict__ w) {
    int i = blockIdx.x * blockDim.x + threadIdx.x;
    if (blockIdx.x == 0 && threadIdx.x < 32) {
        unsigned v = w[2 * threadIdx.x + 1];
        unsigned b = __ballot_sync(0xffffffffu, v != 0u);
        if (threadIdx.x == 0) g_is64 = (b == 0u) ? 1 : 0;
    }
    if (i < NN) g_deg[i] = 0;
    if (i < D) { g_sum[i] = 0.f; g_sumsq[i] = 0.f; }
}

// ---------------- CSR build ----------------
__global__ void k_count(const void* __restrict__ ei) {
    int e = blockIdx.x * blockDim.x + threadIdx.x;
    if (e < EE) {
        int dst = load_idx(ei, EE + e);
        if ((unsigned)dst < (unsigned)NN) atomicAdd(&g_deg[dst], 1);
    }
}

__global__ void k_scan1() {
    __shared__ int s[128];
    int t = threadIdx.x;
    int i = blockIdx.x * 128 + t;
    s[t] = (i < NN) ? g_deg[i] : 0;
    __syncthreads();
    for (int off = 64; off; off >>= 1) {
        if (t < off) s[t] += s[t + off];
        __syncthreads();
    }
    if (t == 0) g_part[blockIdx.x] = s[0];
}

__global__ void k_scan2() {
    __shared__ int s[512];
    int t = threadIdx.x;
    s[t] = (t < NB) ? g_part[t] : 0;
    __syncthreads();
    for (int off = 1; off < 512; off <<= 1) {
        int u = (t >= off) ? s[t - off] : 0;
        __syncthreads();
        s[t] += u;
        __syncthreads();
    }
    if (t < NB) g_part[t] = s[t];
}

__global__ void k_scan3() {
    __shared__ int s[128];
    int t = threadIdx.x;
    int i = blockIdx.x * 128 + t;
    int v = (i < NN) ? g_deg[i] : 0;
    s[t] = v;
    __syncthreads();
    for (int off = 1; off < 128; off <<= 1) {
        int u = (t >= off) ? s[t - off] : 0;
        __syncthreads();
        s[t] += u;
        __syncthreads();
    }
    int base = blockIdx.x ? g_part[blockIdx.x - 1] : 0;
    if (i < NN) {
        int ex = base + s[t] - v;
        g_rowptr[i] = ex;
        g_fill[i]   = ex;
        if (i == NN - 1) g_rowptr[NN] = base + s[t];
    }
}

__global__ void k_fill(const void* __restrict__ ei) {
    int e = blockIdx.x * blockDim.x + threadIdx.x;
    if (e < EE) {
        int dst = load_idx(ei, EE + e);
        if ((unsigned)dst < (unsigned)NN) {
            int pos = atomicAdd(&g_fill[dst], 1);
            if ((unsigned)pos < (unsigned)EE) {
                g_eidx[pos] = e;
                g_src[pos]  = clampN(load_idx(ei, e), NN);
            }
        }
    }
}

// ---------------- Phase A: edge projection GEMM ----------------
// 256 threads / 128 edges per block; thread = (edge r, half h) computing 48 dims.
// acc = 24 ull (48 regs) -> ~3 blocks/SM occupancy instead of 1.
__global__ void __launch_bounds__(256, 3) k_edgemsg(
    const float* __restrict__ ea, const float* __restrict__ We,
    const float* __restrict__ be)
{
    __shared__ __align__(16) float We_s[ED * D];     // 12 KB
    __shared__ __align__(16) float ea_s[128 * 33];   // 16.9 KB
    __shared__ __align__(16) float t_buf[32 * 97];   // 12.4 KB transpose buffer
    __shared__ __align__(16) float be_s[D];

    int tid = threadIdx.x;
    long long e0 = (long long)blockIdx.x * 128;

    for (int i = tid; i < ED * D; i += 256) We_s[i] = We[i];
    if (tid < D) be_s[tid] = be[tid];
    for (int i = tid; i < 128 * ED; i += 256) {
        int r = i >> 5, c = i & 31;
        ea_s[r * 33 + c] = ea[(e0 + r) * ED + c];    // sequential stream, coalesced
    }
    __syncthreads();

    int r = tid >> 1, h = tid & 1;                   // edge row, dim half
    const float* wbase = We_s + h * 48;

    ull acc[24];
#pragma unroll
    for (int j = 0; j < 24; j++) PACK2(acc[j], be_s[h * 48 + 2 * j], be_s[h * 48 + 2 * j + 1]);

    const float* ea_row = ea_s + r * 33;
#pragma unroll 4
    for (int k = 0; k < ED; k++) {
        float hk = ea_row[k];
        ull hk2; PACK2(hk2, hk, hk);
        const ulonglong2* w2 = (const ulonglong2*)(wbase + k * D);
#pragma unroll
        for (int j = 0; j < 12; j++) {
            ulonglong2 w = w2[j];
            FMA2(acc[2 * j],     hk2, w.x, acc[2 * j]);
            FMA2(acc[2 * j + 1], hk2, w.y, acc[2 * j + 1]);
        }
    }

    // 4 quarters of 32 edges: transpose through t_buf, coalesced global stores
    for (int q = 0; q < 4; q++) {
        __syncthreads();
        if ((r >> 5) == q) {
            int base = (r & 31) * 97 + h * 48;       // bank = (row + 16h + col) % 32: conflict-free
#pragma unroll
            for (int j = 0; j < 24; j++) {
                float lo, hi;
                UNPACK2(lo, hi, acc[j]);
                t_buf[base + 2 * j]     = lo;
                t_buf[base + 2 * j + 1] = hi;
            }
        }
        __syncthreads();
        long long gbase = (e0 + (long long)q * 32) * D;
#pragma unroll
        for (int it = 0; it < 12; it++) {            // 32*96/256 = 12
            int f = it * 256 + tid;
            int row = f / D, col = f - row * D;
            g_proj[gbase + f] = t_buf[row * 97 + col];
        }
    }
}

// ---------------- Phase B: pull aggregation (warp per node) ----------------
__global__ void __launch_bounds__(256) k_aggr(const float* __restrict__ x)
{
    int warp = (blockIdx.x * blockDim.x + threadIdx.x) >> 5;
    int lane = threadIdx.x & 31;
    if (warp >= NN) return;

    int node = warp;
    int beg = g_rowptr[node], end = g_rowptr[node + 1];
    float a0 = 0.f, a1 = 0.f, a2 = 0.f;
    for (int p = beg; p < end; p++) {
        int e   = clampN(g_eidx[p], EE);
        int src = g_src[p];
        const float* pr = g_proj + (long long)e * D;
        const float* xs = x + (long long)src * D;
        a0 += fmaxf(xs[lane]      + pr[lane],      0.f);
        a1 += fmaxf(xs[lane + 32] + pr[lane + 32], 0.f);
        a2 += fmaxf(xs[lane + 64] + pr[lane + 64], 0.f);
    }
    const float* xn = x + (long long)node * D;
    g_h[node * D + lane]      = xn[lane]      + a0;
    g_h[node * D + lane + 32] = xn[lane + 32] + a1;
    g_h[node * D + lane + 64] = xn[lane + 64] + a2;
}

// ---------------- dense layer (FFMA2): stage 0: g_h->g_h1 (ReLU); stage 1: g_h1->g_h2 (+stats) ----------------
__global__ void __launch_bounds__(128) k_mlp(
    const float* __restrict__ W, const float* __restrict__ bias, int stage)
{
    __shared__ __align__(16) float Ws[32 * D];
    __shared__ __align__(16) float hs[128 * 33];

    const float* hin  = (stage == 0) ? g_h  : g_h1;
    float*       hout = (stage == 0) ? g_h1 : g_h2;

    int tid  = threadIdx.x;
    int base = blockIdx.x * 128;
    int node = base + tid;
    bool valid = node < NN;

    ull acc[48];
#pragma unroll
    for (int j = 0; j < 48; j++) { float c0 = bias[2 * j], c1 = bias[2 * j + 1]; PACK2(acc[j], c0, c1); }

    for (int kt = 0; kt < 3; kt++) {
        for (int i = tid; i < 32 * D; i += 128) Ws[i] = W[kt * 32 * D + i];
        for (int i = tid; i < 128 * 32; i += 128) {
            int r = i >> 5, kk = i & 31;
            int nd = base + r;
            hs[r * 33 + kk] = (nd < NN) ? hin[(long long)nd * D + kt * 32 + kk] : 0.f;
        }
        __syncthreads();

#pragma unroll 2
        for (int kk = 0; kk < 32; kk++) {
            float hk = hs[tid * 33 + kk];
            ull hk2; PACK2(hk2, hk, hk);
            const ulonglong2* w2 = (const ulonglong2*)(Ws + kk * D);
#pragma unroll
            for (int j = 0; j < 24; j++) {
                ulonglong2 w = w2[j];
                FMA2(acc[2 * j],     hk2, w.x, acc[2 * j]);
                FMA2(acc[2 * j + 1], hk2, w.y, acc[2 * j + 1]);
            }
        }
        __syncthreads();
    }

    float v[D];
#pragma unroll
    for (int j = 0; j < 48; j++) UNPACK2(v[2 * j], v[2 * j + 1], acc[j]);

    if (stage == 0) {
#pragma unroll
        for (int j = 0; j < D; j++) v[j] = fmaxf(v[j], 0.f);
    }
    if (valid) {
        float4* out4 = (float4*)(hout + (long long)node * D);
#pragma unroll
        for (int j4 = 0; j4 < D / 4; j4++)
            out4[j4] = make_float4(v[4 * j4], v[4 * j4 + 1], v[4 * j4 + 2], v[4 * j4 + 3]);
    }
    if (stage == 1) {
#pragma unroll
        for (int j = 0; j < D; j++) {
            float s1 = valid ? v[j] : 0.f;
            float s2 = s1 * s1;
            for (int off = 16; off; off >>= 1) {
                s1 += __shfl_down_sync(0xffffffffu, s1, off);
                s2 += __shfl_down_sync(0xffffffffu, s2, off);
            }
            if ((tid & 31) == 0) {
                atomicAdd(&g_sum[j],   s1);
                atomicAdd(&g_sumsq[j], s2);
            }
        }
    }
}

// ---------------- batchnorm + relu ----------------
__global__ void k_bn(const float* __restrict__ gamma,
                     const float* __restrict__ beta,
                     float* __restrict__ out)
{
    int i = blockIdx.x * blockDim.x + threadIdx.x;
    const int TOT4 = NN * D / 4;
    if (i >= TOT4) return;
    int c = (i * 4) % D;
    const float invN = 1.0f / (float)NN;
    float4 h = ((const float4*)g_h2)[i];
    float hv[4] = {h.x, h.y, h.z, h.w};
    float o[4];
#pragma unroll
    for (int u = 0; u < 4; u++) {
        int cc = c + u;
        float mean = g_sum[cc] * invN;
        float var  = g_sumsq[cc] * invN - mean * mean;
        float inv  = rsqrtf(var + 1e-5f);
        o[u] = fmaxf((hv[u] - mean) * inv * gamma[cc] + beta[cc], 0.f);
    }
    ((float4*)out)[i] = make_float4(o[0], o[1], o[2], o[3]);
}

// ---------------- launch (edgemsg at profiled slot 3) ----------------
extern "C" void kernel_launch(void* const* d_in, const int* in_sizes, int n_in,
                              void* d_out, int out_size)
{
    const float* x     = (const float*)d_in[0];
    const void*  ei    = d_in[1];
    const float* ea    = (const float*)d_in[2];
    const float* We    = (const float*)d_in[3];
    const float* be    = (const float*)d_in[4];
    const float* W1    = (const float*)d_in[5];
    const float* b1    = (const float*)d_in[6];
    const float* W2    = (const float*)d_in[7];
    const float* b2    = (const float*)d_in[8];
    const float* gamma = (const float*)d_in[9];
    const float* beta  = (const float*)d_in[10];
    float*       out   = (float*)d_out;

    k_init   <<<(NN + 255) / 256, 256>>>((const unsigned int*)ei);   // 0
    k_count  <<<(EE + 255) / 256, 256>>>(ei);                        // 1
    k_scan1  <<<NB, 128>>>();                                        // 2
    k_edgemsg<<<EE / 128, 256>>>(ea, We, be);                        // 3  <- profiled slot
    k_scan2  <<<1, 512>>>();                                         // 4
    k_scan3  <<<NB, 128>>>();                                        // 5
    k_fill   <<<(EE + 255) / 256, 256>>>(ei);                        // 6
    k_aggr   <<<NN / 8, 256>>>(x);                                   // 7
    k_mlp    <<<(NN + 127) / 128, 128>>>(W1, b1, 0);                 // 8
    k_mlp    <<<(NN + 127) / 128, 128>>>(W2, b2, 1);                 // 9
    k_bn     <<<(NN * D / 4 + 255) / 256, 256>>>(gamma, beta, out);  // 10
}